// round 17
// baseline (speedup 1.0000x reference)
#include <cuda_runtime.h>

// Problem constants (fixed by the dataset)
#define NB   64          // batch
#define T1   4097        // maxT+1
#define MAXT 4096
#define HB   16          // hidden states
#define NA   18          // actions
#define CL   64          // chunk length (steps per chunk)
#define BPB  8           // chunk blocks per batch
#define NMB  8           // block-level matrices per batch (after block fold)

// Scratch: per (batch, block) folded transfer matrix (512 steps each).
__device__ float g_mats[NB * NMB * HB * HB];   // 512 KB
__device__ float g_lam[NB * NMB * HB];
__device__ float g_partial[NB];
__device__ int   g_cnt[NB];     // zero-init; self-resetting each call
__device__ int   g_cnt2;        // zero-init; self-resetting each call

__device__ __forceinline__ float ldcg(const float* p) {
    float v; asm volatile("ld.global.cg.f32 %0,[%1];" : "=f"(v) : "l"(p)); return v;
}
__device__ __forceinline__ float4 ldcg4(const float* p) {
    float4 v;
    asm volatile("ld.global.cg.v4.f32 {%0,%1,%2,%3},[%4];"
                 : "=f"(v.x), "=f"(v.y), "=f"(v.z), "=f"(v.w) : "l"(p));
    return v;
}

// Prefetch bank: 8 steps of (stop.xy, start, action_logp) per lane.
struct PFB { float2 s[8]; float t[8]; float a[8]; };

__device__ __forceinline__ void load_group(
    int g0, int nact, unsigned idx16_0,
    const float2* __restrict__ stop2, const float* __restrict__ startl,
    const float* __restrict__ alogp, const int* __restrict__ sa,
    PFB& B)
{
#pragma unroll
    for (int u = 0; u < 8; ++u) {
        int t = g0 + u;
        if (t < nact) {
            unsigned idx = idx16_0 + (unsigned)t * 16u;
            B.s[u] = __ldg(stop2 + idx);                         // (beta, omb)
            B.t[u] = __ldg(startl + idx);                        // start
            B.a[u] = __ldg(alogp + idx * 18u + (unsigned)sa[t]); // action logp
        } else {
            B.s[u] = make_float2(0.f, 0.f); B.t[u] = 0.f; B.a[u] = 0.f;
        }
    }
}

// Per step i (exact linear map):
//   s     = sum_j exp(beta_j) * p[j]
//   p[k] <- exp(al_k+start_k)*s + exp(al_k+omb_k)*p[k]
// Every 4 steps: p /= s, lam += log(s)  (conditioning; p*e^lam invariant).
__device__ __forceinline__ void consume_group(
    int g0, int nsteps, int nact, int c, float* __restrict__ vb2,
    PFB& B, float (&p)[HB], float& lam)
{
#pragma unroll
    for (int u = 0; u < 8; ++u) {
        int t = g0 + u;
        if (t >= nsteps) return;   // nsteps is warp-uniform
        float eb   = __expf(B.s[u].x);
        float easv = __expf(B.a[u] + B.t[u]);
        float eaov = __expf(B.a[u] + B.s[u].y);
        float* vb = vb2 + (u & 1) * 48;
        vb[c]      = eb;
        vb[16 + c] = easv;
        vb[32 + c] = eaov;
        __syncwarp();
        const float4* EB = (const float4*)vb;
        float4 e0 = EB[0], e1 = EB[1], e2 = EB[2], e3 = EB[3];
        float t0 = fmaf(e0.x, p[0],  e0.y * p[1])  + fmaf(e0.z, p[2],  e0.w * p[3]);
        float t1 = fmaf(e1.x, p[4],  e1.y * p[5])  + fmaf(e1.z, p[6],  e1.w * p[7]);
        float t2 = fmaf(e2.x, p[8],  e2.y * p[9])  + fmaf(e2.z, p[10], e2.w * p[11]);
        float t3 = fmaf(e3.x, p[12], e3.y * p[13]) + fmaf(e3.z, p[14], e3.w * p[15]);
        float s = (t0 + t1) + (t2 + t3);
        if (t < nact) {            // uniform within each half-warp
            const float4* EA = (const float4*)(vb + 16);
            const float4* EO = (const float4*)(vb + 32);
            float4 a0 = EA[0], a1 = EA[1], a2 = EA[2], a3 = EA[3];
            float4 o0 = EO[0], o1 = EO[1], o2 = EO[2], o3 = EO[3];
            p[0]  = fmaf(o0.x, p[0],  a0.x * s);
            p[1]  = fmaf(o0.y, p[1],  a0.y * s);
            p[2]  = fmaf(o0.z, p[2],  a0.z * s);
            p[3]  = fmaf(o0.w, p[3],  a0.w * s);
            p[4]  = fmaf(o1.x, p[4],  a1.x * s);
            p[5]  = fmaf(o1.y, p[5],  a1.y * s);
            p[6]  = fmaf(o1.z, p[6],  a1.z * s);
            p[7]  = fmaf(o1.w, p[7],  a1.w * s);
            p[8]  = fmaf(o2.x, p[8],  a2.x * s);
            p[9]  = fmaf(o2.y, p[9],  a2.y * s);
            p[10] = fmaf(o2.z, p[10], a2.z * s);
            p[11] = fmaf(o2.w, p[11], a2.w * s);
            p[12] = fmaf(o3.x, p[12], a3.x * s);
            p[13] = fmaf(o3.y, p[13], a3.y * s);
            p[14] = fmaf(o3.z, p[14], a3.z * s);
            p[15] = fmaf(o3.w, p[15], a3.w * s);
            if ((t & 3) == 3) {
                float r = __fdividef(1.0f, s);
                lam += __logf(s);
#pragma unroll
                for (int k = 0; k < HB; ++k) p[k] *= r;
            }
        }
    }
}

// Tree product: C_true = A_true * P_true (A later, P earlier).
__device__ __forceinline__ void mat_product2(
    const float* __restrict__ srcM, const float* __restrict__ srcLam,
    float* __restrict__ dstM, float* __restrict__ dstLam,
    int pidx, int lane, float* __restrict__ sw, bool from_gmem)
{
    const int c = lane & 15;
    const int h = lane >> 4;                    // rows [8h, 8h+8)
    const float* Pm = srcM + (size_t)(2 * pidx) * 256;
    const float* Am = srcM + (size_t)(2 * pidx + 1) * 256;
    float lamP, lamA;
    if (from_gmem) {
        lamP = ldcg(srcLam + (2 * pidx) * 16 + c);
        lamA = ldcg(srcLam + (2 * pidx + 1) * 16 + c);
    } else {
        lamP = srcLam[(2 * pidx) * 16 + c];
        lamA = srcLam[(2 * pidx + 1) * 16 + c];
    }
    float mA = lamA;
    mA = fmaxf(mA, __shfl_xor_sync(0xffffffffu, mA, 1));
    mA = fmaxf(mA, __shfl_xor_sync(0xffffffffu, mA, 2));
    mA = fmaxf(mA, __shfl_xor_sync(0xffffffffu, mA, 4));
    mA = fmaxf(mA, __shfl_xor_sync(0xffffffffu, mA, 8));
    if (lane < 16) sw[c] = __expf(lamA - mA);
    __syncwarp();
    float w[16];
#pragma unroll
    for (int j = 0; j < 16; ++j)
        w[j] = sw[j] * (from_gmem ? ldcg(Pm + j * 16 + c) : Pm[j * 16 + c]);
    __syncwarp();
    float Cv[8];
#pragma unroll
    for (int k8 = 0; k8 < 8; ++k8) {
        float4 a0, a1, a2, a3;
        const float* Ar = Am + (h * 8 + k8) * 16;
        if (from_gmem) { a0 = ldcg4(Ar); a1 = ldcg4(Ar + 4); a2 = ldcg4(Ar + 8); a3 = ldcg4(Ar + 12); }
        else { const float4* A4 = (const float4*)Ar; a0 = A4[0]; a1 = A4[1]; a2 = A4[2]; a3 = A4[3]; }
        float d0 = fmaf(a0.x, w[0],  a0.y * w[1])  + fmaf(a0.z, w[2],  a0.w * w[3]);
        float d1 = fmaf(a1.x, w[4],  a1.y * w[5])  + fmaf(a1.z, w[6],  a1.w * w[7]);
        float d2 = fmaf(a2.x, w[8],  a2.y * w[9])  + fmaf(a2.z, w[10], a2.w * w[11]);
        float d3 = fmaf(a3.x, w[12], a3.y * w[13]) + fmaf(a3.z, w[14], a3.w * w[15]);
        Cv[k8] = (d0 + d1) + (d2 + d3);
    }
    float s = Cv[0];
#pragma unroll
    for (int k8 = 1; k8 < 8; ++k8) s = fmaxf(s, Cv[k8]);
    s = fmaxf(s, __shfl_xor_sync(0xffffffffu, s, 16));   // combine halves
    float r = __fdividef(1.0f, s);
#pragma unroll
    for (int k8 = 0; k8 < 8; ++k8)
        dstM[pidx * 256 + (h * 8 + k8) * 16 + c] = Cv[k8] * r;
    if (lane < 16) dstLam[pidx * 16 + c] = lamP + mA + __logf(s);
}

// ===========================================================================
// Single fused kernel: 8 blocks per batch, 4 warps per block.
// Each warp: 2 chunks (halves) -> warp fold. Block: 4 warp-mats -> 1 block-mat.
// Last block per batch: 3-level tree over the 8 block-mats + finalization.
// Last finisher overall writes *out (fixed summation order -> deterministic).
// ===========================================================================
__global__ __launch_bounds__(128) void hmm_fused(
    const float* __restrict__ alogp,
    const float* __restrict__ stopl,
    const float* __restrict__ startl,
    const int* __restrict__ actions,
    const int* __restrict__ lengths,
    float* __restrict__ out)
{
    const int wib  = threadIdx.x >> 5;
    const int lane = threadIdx.x & 31;
    const int b    = blockIdx.x >> 3;          // 64 batches
    const int blk  = blockIdx.x & 7;           // 8 blocks per batch
    const int pr   = blk * 4 + wib;            // 32 chunk-pairs per batch
    const int sub  = lane >> 4;
    const int c    = lane & 15;
    const int ch   = pr * 2 + sub;
    const int i0   = 1 + ch * CL;

    __shared__ int s_act[4][2 * CL];
    __shared__ __align__(16) float s_vec[4][2][2][3 * HB];
    __shared__ __align__(16) float s_m1[4][HB][HB + 1];
    __shared__ float s_lam1[4][HB];
    __shared__ __align__(16) float bm[6 * 256];
    __shared__ float lamB[6 * 16];
    __shared__ __align__(16) float sw[4][16];
    __shared__ int s_last, s_last2;

    const int len = lengths[b];

    // ---- chunk phase (one chunk per half-warp) ----
    int cnt  = min(CL, MAXT - i0);
    int nact = max(0, min(len - i0, cnt));
    const int i0p  = 1 + pr * 2 * CL;
    int n0 = max(0, min(len - i0p, min(CL, MAXT - i0p)));
    int n1 = max(0, min(len - (i0p + CL), min(CL, MAXT - (i0p + CL))));
    int nsteps = max(n0, n1);

    int totA = min(2 * CL, MAXT - i0p);
    for (int idx = lane; idx < totA; idx += 32)
        s_act[wib][idx] = actions[(size_t)b * MAXT + i0p + idx];
    __syncwarp();

    float p[HB];
#pragma unroll
    for (int k = 0; k < HB; ++k) p[k] = (k == c) ? 1.0f : 0.0f;
    float lam = 0.0f;

    if (nsteps > 0) {
        const unsigned idx16_0 = ((unsigned)b * T1 + (unsigned)i0) * 16u + (unsigned)c;
        const float2* stop2 = (const float2*)stopl;
        const int* sa = &s_act[wib][sub * CL];
        float* vb2 = &s_vec[wib][sub][0][0];

        PFB B0, B1;
        load_group(0, nact, idx16_0, stop2, startl, alogp, sa, B0);
        for (int g0 = 0; g0 < nsteps; g0 += 16) {
            load_group(g0 + 8, nact, idx16_0, stop2, startl, alogp, sa, B1);
            consume_group(g0, nsteps, nact, c, vb2, B0, p, lam);
            if (g0 + 8 < nsteps) {
                load_group(g0 + 16, nact, idx16_0, stop2, startl, alogp, sa, B0);
                consume_group(g0 + 8, nsteps, nact, c, vb2, B1, p, lam);
            }
        }
    }

    // ---- warp fold: R_true = M1_true * M0_true -> smem bm[wib] ----
    __syncwarp();
    if (sub == 1) {
#pragma unroll
        for (int k = 0; k < HB; ++k) s_m1[wib][c][k] = p[k];   // row c = column c of M1hat
        s_lam1[wib][c] = lam;
    }
    __syncwarp();
    if (sub == 0) {
        float m1 = s_lam1[wib][0];
#pragma unroll
        for (int j = 1; j < HB; ++j) m1 = fmaxf(m1, s_lam1[wib][j]);
        float R[HB];
#pragma unroll
        for (int k = 0; k < HB; ++k) R[k] = 0.0f;
#pragma unroll
        for (int j = 0; j < HB; ++j) {
            float wj = p[j] * __expf(s_lam1[wib][j] - m1);
            const float* Aj = &s_m1[wib][j][0];
#pragma unroll
            for (int k = 0; k < HB; ++k) R[k] = fmaf(wj, Aj[k], R[k]);
        }
        float s = R[0];
#pragma unroll
        for (int k = 1; k < HB; ++k) s = fmaxf(s, R[k]);
        float r = __fdividef(1.0f, s);
#pragma unroll
        for (int k = 0; k < HB; ++k)
            bm[wib * 256 + k * 16 + c] = R[k] * r;
        lamB[wib * 16 + c] = lam + m1 + __logf(s);
    }
    __syncthreads();

    // ---- block fold: 4 warp-mats -> 2 -> 1 -> gmem ----
    if (wib < 2)
        mat_product2(bm, lamB, bm + 4 * 256, lamB + 4 * 16, wib, lane, sw[wib], false);
    __syncthreads();
    if (wib == 0) {
        __shared__ __align__(16) float fin[256];
        __shared__ float finLam[16];
        mat_product2(bm + 4 * 256, lamB + 4 * 16, fin, finLam, 0, lane, sw[0], false);
        float* gm = g_mats + (size_t)(b * NMB + blk) * 256;
#pragma unroll
        for (int k8 = 0; k8 < 8; ++k8)
            gm[((lane >> 4) * 8 + k8) * 16 + c] = fin[((lane >> 4) * 8 + k8) * 16 + c];
        if (lane < 16)
            g_lam[(size_t)(b * NMB + blk) * 16 + c] = finLam[c];
    }

    // ---- last-block election (per batch) ----
    __threadfence();
    __syncthreads();
    if (threadIdx.x == 0) {
        int old = atomicAdd(&g_cnt[b], 1);
        s_last = (old == BPB - 1);
        if (old == BPB - 1) g_cnt[b] = 0;      // self-reset for graph replay
    }
    __syncthreads();
    if (!s_last) return;

    // ---- tree combine over the 8 block-mats (this block; 4 warps) ----
    // bm is dead -> reuse: L1 out = bm[0..1023] (4 mats), L2 out = bm[4*256..]
    const float* gM = g_mats + (size_t)b * NMB * 256;
    const float* gL = g_lam  + (size_t)b * NMB * 16;
    float* X = bm;            float* lamX = lamB;            // 4 mats
    float* Y = bm + 4 * 256;  float* lamY = lamB + 4 * 16;   // 2 mats

    // L1: 8 -> 4 (gmem -> X)
    mat_product2(gM, gL, X, lamX, wib, lane, sw[wib], true);
    __syncthreads();
    // L2: 4 -> 2
    if (wib < 2) mat_product2(X, lamX, Y, lamY, wib, lane, sw[wib], false);
    __syncthreads();
    // L3: 2 -> 1  (final in X[0..255], lam in lamX[0..15])
    if (wib == 0) mat_product2(Y, lamY, X, lamX, 0, lane, sw[0], false);
    __syncthreads();

    if (wib == 0) {
        const size_t rb = (size_t)b * T1;
        const int a0i = actions[(size_t)b * MAXT];

        float f0 = startl[rb * 16 + c] + alogp[(rb * 16 + (size_t)c) * 18 + a0i];
        float t = lamX[c] + f0;
        float F0 = t;
        F0 = fmaxf(F0, __shfl_xor_sync(0xffffffffu, F0, 1));
        F0 = fmaxf(F0, __shfl_xor_sync(0xffffffffu, F0, 2));
        F0 = fmaxf(F0, __shfl_xor_sync(0xffffffffu, F0, 4));
        F0 = fmaxf(F0, __shfl_xor_sync(0xffffffffu, F0, 8));
        if (lane < 16) sw[0][c] = __expf(t - F0);
        __syncwarp();
        const float4* M4 = (const float4*)X;
        const float4* W4 = (const float4*)sw[0];
        float4 m0 = M4[c * 4 + 0], m1 = M4[c * 4 + 1];
        float4 m2 = M4[c * 4 + 2], m3 = M4[c * 4 + 3];
        float4 w0 = W4[0], w1 = W4[1], w2 = W4[2], w3 = W4[3];
        float d0 = fmaf(m0.x, w0.x, m0.y * w0.y) + fmaf(m0.z, w0.z, m0.w * w0.w);
        float d1 = fmaf(m1.x, w1.x, m1.y * w1.y) + fmaf(m1.z, w1.z, m1.w * w1.w);
        float d2 = fmaf(m2.x, w2.x, m2.y * w2.y) + fmaf(m2.z, w2.z, m2.w * w2.w);
        float d3 = fmaf(m3.x, w3.x, m3.y * w3.y) + fmaf(m3.z, w3.z, m3.w * w3.w);
        float v = (d0 + d1) + (d2 + d3);      // lane c: (M w)_c

        float u = stopl[((rb + (size_t)len) * 16 + (size_t)c) * 2];
        float mS = u;
        mS = fmaxf(mS, __shfl_xor_sync(0xffffffffu, mS, 1));
        mS = fmaxf(mS, __shfl_xor_sync(0xffffffffu, mS, 2));
        mS = fmaxf(mS, __shfl_xor_sync(0xffffffffu, mS, 4));
        mS = fmaxf(mS, __shfl_xor_sync(0xffffffffu, mS, 8));
        float term = __expf(u - mS) * v;
        term += __shfl_xor_sync(0xffffffffu, term, 1);
        term += __shfl_xor_sync(0xffffffffu, term, 2);
        term += __shfl_xor_sync(0xffffffffu, term, 4);
        term += __shfl_xor_sync(0xffffffffu, term, 8);

        if (lane == 0) {
            g_partial[b] = -(F0 + mS + __logf(term));
            __threadfence();
            int old2 = atomicAdd(&g_cnt2, 1);
            s_last2 = (old2 == NB - 1);
            if (old2 == NB - 1) g_cnt2 = 0;    // self-reset
        }
    }
    __syncthreads();

    // ---- final reduction over batches (exactly one block reaches here last) ----
    if (s_last2 && wib == 0) {
        float v = ldcg(&g_partial[lane]) + ldcg(&g_partial[lane + 32]);
        v += __shfl_xor_sync(0xffffffffu, v, 1);
        v += __shfl_xor_sync(0xffffffffu, v, 2);
        v += __shfl_xor_sync(0xffffffffu, v, 4);
        v += __shfl_xor_sync(0xffffffffu, v, 8);
        v += __shfl_xor_sync(0xffffffffu, v, 16);
        if (lane == 0) *out = v;
    }
}

extern "C" void kernel_launch(void* const* d_in, const int* in_sizes, int n_in,
                              void* d_out, int out_size)
{
    const float* alogp   = (const float*)d_in[0];
    const float* stopl   = (const float*)d_in[1];
    const float* startl  = (const float*)d_in[2];
    const int*   actions = (const int*)d_in[3];
    const int*   lengths = (const int*)d_in[4];
    float* out = (float*)d_out;

    hmm_fused<<<NB * BPB, 128>>>(alogp, stopl, startl, actions, lengths, out);
}